// round 12
// baseline (speedup 1.0000x reference)
#include <cuda_runtime.h>
#include <cuda_bf16.h>
#include <cstdint>

// Indexer gather: out[i, :] = items[min((int)(clamp(indices[i],0,1)*1024), 1023), :]
// indices: [1048576] f32, items: [1024, 256] f32, out: [1048576, 256] f32.
//
// R7: R4 layout (best: 143.6us) with DEFAULT-policy stores instead of __stcs.
// Theory: evict-first (.cs) forces eager per-line writeback scheduling; the
// default policy lets L2 aggregate dirty lines into larger, better-paged HBM
// writeback bursts. The items table (1 MB) stays L2-resident by reference
// frequency (~1000 touches/line per kernel), so it no longer needs the .cs
// protection on the write stream.
// Layout per thread: one output row's 4 float4 chunks at cols (tid&15)+16i,
// one L1-broadcast index load -> 4 independent L2-hit gathers -> 4 stores.

static constexpr int N_INDICES   = 1048576;
static constexpr int D_ITEM      = 256;
static constexpr int N_ITEMS     = 1024;
static constexpr int VEC_PER_ROW = D_ITEM / 4;                                  // 64
static constexpr int ITERS   = 4;
static constexpr int THREADS = 256;
static constexpr long long TOTAL_THREADS = (long long)N_INDICES * (VEC_PER_ROW / ITERS); // 2^24

__global__ __launch_bounds__(THREADS, 8)
void indexer_gather_kernel(const float* __restrict__ indices,
                           const float4* __restrict__ items,
                           float4* __restrict__ out)
{
    unsigned tid = blockIdx.x * blockDim.x + threadIdx.x;   // < 2^24
    unsigned row = tid >> 4;          // output/index row   (< 2^20)
    unsigned c0  = tid & 15u;         // base float4 column

    // One index load per thread (broadcast within each 16-lane group, L1-hit).
    float x = __ldg(&indices[row]);
    x = fminf(fmaxf(x, 0.0f), 1.0f) * (float)N_ITEMS;     // x in [0, 1024]
    int closest = min((int)x, N_ITEMS - 1);               // trunc == floor (x >= 0)
    const float4* irow = items + (unsigned)closest * VEC_PER_ROW;

    float4 val[ITERS];
    #pragma unroll
    for (int i = 0; i < ITERS; i++) {
        val[i] = __ldg(&irow[c0 + 16u * i]);     // 4 independent L2-hit gathers
    }

    float4* orow = out + (unsigned long long)row * VEC_PER_ROW;
    #pragma unroll
    for (int i = 0; i < ITERS; i++) {
        orow[c0 + 16u * i] = val[i];             // default-policy coalesced stores
    }
}

extern "C" void kernel_launch(void* const* d_in, const int* in_sizes, int n_in,
                              void* d_out, int out_size)
{
    const float*  indices = (const float*)d_in[0];
    const float4* items   = (const float4*)d_in[1];
    float4*       out     = (float4*)d_out;

    const unsigned blocks = (unsigned)(TOTAL_THREADS / THREADS);   // 65536
    indexer_gather_kernel<<<blocks, THREADS>>>(indices, items, out);
}

// round 13
// speedup vs baseline: 1.0393x; 1.0393x over previous
#include <cuda_runtime.h>
#include <cuda_bf16.h>
#include <cstdint>

// Indexer gather: out[i, :] = items[min((int)(clamp(indices[i],0,1)*1024), 1023), :]
// indices: [1048576] f32, items: [1024, 256] f32, out: [1048576, 256] f32.
//
// R8 FINAL = R4 config (best measured: 143.6us, ~93% of HBM write spec) with
// the trunc-cast cleanup. Per thread: one output row's 4 float4 chunks at
// cols (tid&15)+16i -> one L1-broadcast index load, 4 independent L2-hit
// gathers (items table, 1 MB, fully L2-resident), 4 __stcs streaming stores
// (evict-first writeback proved fastest for the pure 1.07 GB output stream;
// default policy regressed in R7).
// Explored & refuted: deeper MLP (R3: reg/occ collapse), persistent grid
// (R5: loop serializes the stream), index-latency pairing (R6: neutral),
// default store policy (R7: slower). Kernel is pinned at the HBM-write
// roofline; DRAM traffic == mandatory writes only.

static constexpr int N_INDICES   = 1048576;
static constexpr int D_ITEM      = 256;
static constexpr int N_ITEMS     = 1024;
static constexpr int VEC_PER_ROW = D_ITEM / 4;                                  // 64
static constexpr int ITERS   = 4;
static constexpr int THREADS = 256;
static constexpr long long TOTAL_THREADS = (long long)N_INDICES * (VEC_PER_ROW / ITERS); // 2^24

__global__ __launch_bounds__(THREADS, 8)
void indexer_gather_kernel(const float* __restrict__ indices,
                           const float4* __restrict__ items,
                           float4* __restrict__ out)
{
    unsigned tid = blockIdx.x * blockDim.x + threadIdx.x;   // < 2^24
    unsigned row = tid >> 4;          // output/index row   (< 2^20)
    unsigned c0  = tid & 15u;         // base float4 column

    // One index load per thread (broadcast within each 16-lane group).
    float x = __ldg(&indices[row]);
    x = fminf(fmaxf(x, 0.0f), 1.0f) * (float)N_ITEMS;     // x in [0, 1024]
    int closest = min((int)x, N_ITEMS - 1);               // trunc == floor (x >= 0)
    const float4* irow = items + (unsigned)closest * VEC_PER_ROW;

    float4 val[ITERS];
    #pragma unroll
    for (int i = 0; i < ITERS; i++) {
        val[i] = __ldg(&irow[c0 + 16u * i]);     // 4 independent L2-hit gathers
    }

    float4* orow = out + (unsigned long long)row * VEC_PER_ROW;
    #pragma unroll
    for (int i = 0; i < ITERS; i++) {
        __stcs(&orow[c0 + 16u * i], val[i]);     // streaming stores, fully coalesced
    }
}

extern "C" void kernel_launch(void* const* d_in, const int* in_sizes, int n_in,
                              void* d_out, int out_size)
{
    const float*  indices = (const float*)d_in[0];
    const float4* items   = (const float4*)d_in[1];
    float4*       out     = (float4*)d_out;

    const unsigned blocks = (unsigned)(TOTAL_THREADS / THREADS);   // 65536
    indexer_gather_kernel<<<blocks, THREADS>>>(indices, items, out);
}